// round 5
// baseline (speedup 1.0000x reference)
#include <cuda_runtime.h>
#include <cuda_fp8.h>
#include <cstdint>

// Problem constants
#define NN 8192
#define DD 128
static constexpr float MARGIN = 1.0f;

// Tiling: one CTA tile = 128x128, full K=128 in smem at once (fp8 = 16KB/tile)
static constexpr int BM = 128, BN = 128;
static constexpr int THREADS = 256;           // 8 warps: 2 (m) x 4 (n)
static constexpr int MAXP = 1 << 20;

// ---------------------------------------------------------------------------
// Device globals
// ---------------------------------------------------------------------------
__device__ float g_V[NN];
__device__ float g_loss_sum;
__device__ int   g_pair_cnt;
__device__ int   g_pi[MAXP];
__device__ int   g_pj[MAXP];
__device__ __align__(16) uint8_t g_A8[NN * DD];
__device__ __align__(16) uint8_t g_B8[NN * DD];

// ---------------------------------------------------------------------------
// PTX helpers
// ---------------------------------------------------------------------------
__device__ __forceinline__ void ldsm_x4(uint32_t& r0, uint32_t& r1, uint32_t& r2, uint32_t& r3,
                                        uint32_t saddr) {
    asm volatile("ldmatrix.sync.aligned.m8n8.x4.shared.b16 {%0,%1,%2,%3}, [%4];"
                 : "=r"(r0), "=r"(r1), "=r"(r2), "=r"(r3) : "r"(saddr));
}
// fp8 e4m3 MMA: 16x8x32, f32 accumulate
__device__ __forceinline__ void mma_fp8(float* d,
                                        uint32_t a0, uint32_t a1, uint32_t a2, uint32_t a3,
                                        uint32_t b0, uint32_t b1) {
    asm volatile(
        "mma.sync.aligned.m16n8k32.row.col.f32.e4m3.e4m3.f32 "
        "{%0,%1,%2,%3}, {%4,%5,%6,%7}, {%8,%9}, {%0,%1,%2,%3};"
        : "+f"(d[0]), "+f"(d[1]), "+f"(d[2]), "+f"(d[3])
        : "r"(a0), "r"(a1), "r"(a2), "r"(a3), "r"(b0), "r"(b1));
}

// ---------------------------------------------------------------------------
// Kernel 0: f32 -> e4m3 conversion + accumulator zeroing (every replay)
// ---------------------------------------------------------------------------
__global__ void k_convert(const float* __restrict__ A, const float* __restrict__ B) {
    int t = blockIdx.x * blockDim.x + threadIdx.x;     // 0 .. NN*DD/4-1
    float4 va = ((const float4*)A)[t];
    float4 vb = ((const float4*)B)[t];
    __nv_fp8x4_e4m3 qa(va);
    __nv_fp8x4_e4m3 qb(vb);
    ((uint32_t*)g_A8)[t] = *reinterpret_cast<uint32_t*>(&qa);
    ((uint32_t*)g_B8)[t] = *reinterpret_cast<uint32_t*>(&qb);
    if (t < NN) g_V[t] = 0.0f;
    if (t == 0) { g_loss_sum = 0.0f; g_pair_cnt = 0; }
}

// ---------------------------------------------------------------------------
// Kernel 1: fp8 mma.sync GEMM S = A * B^T (f32 accum), fused epilogue:
//   V[i] += sum_{labels differ} exp(MARGIN + S_ij); capture positive (i,j).
// Smem: [row][16B-chunk ^ (row&7)] swizzle, 128 B per row (full K).
// ---------------------------------------------------------------------------
__global__ __launch_bounds__(THREADS, 2)
void k_gemm(const int* __restrict__ labels) {
    __shared__ __align__(16) uint8_t As[BM * DD];   // 16 KB
    __shared__ __align__(16) uint8_t Bs[BN * DD];   // 16 KB
    __shared__ float sV[BM];
    __shared__ int   sLi[BM];
    __shared__ int   sLj[BN];

    const int tid  = threadIdx.x;
    const int wid  = tid >> 5;
    const int lane = tid & 31;
    const int g    = lane >> 2;       // 0..7
    const int l4   = lane & 3;        // 0..3
    const int wm   = wid >> 2;        // 0..1 -> m offset 64*wm
    const int wn   = wid & 3;         // 0..3 -> n offset 32*wn
    const int bi   = blockIdx.y * BM;
    const int bj   = blockIdx.x * BN;

    if (tid < BM) { sV[tid] = 0.0f; sLi[tid] = labels[bi + tid]; }
    else if (tid < BM + BN) { sLj[tid - BM] = labels[bj + (tid - BM)]; }

    // Load full tiles: 1024 uint4 per matrix, 4 per thread.
#pragma unroll
    for (int t = 0; t < 4; ++t) {
        int idx = tid + t * THREADS;           // 0..1023
        int row = idx >> 3;                    // 0..127
        int cc  = idx & 7;                     // 16B chunk 0..7
        int sw  = cc ^ (row & 7);
        *(uint4*)&As[row * DD + sw * 16] =
            *(const uint4*)&g_A8[(size_t)(bi + row) * DD + cc * 16];
        *(uint4*)&Bs[row * DD + sw * 16] =
            *(const uint4*)&g_B8[(size_t)(bj + row) * DD + cc * 16];
    }
    __syncthreads();

    const uint32_t as_base = (uint32_t)__cvta_generic_to_shared(As);
    const uint32_t bs_base = (uint32_t)__cvta_generic_to_shared(Bs);

    // ldmatrix lane->address precompute: matrix q = lane>>3, row-in-matrix rr.
    const int q  = lane >> 3;
    const int rr = lane & 7;
    // A x4 per m16 block: q0=(rows0-7,kLo16B) q1=(rows8-15,kLo) q2=(rows0-7,kHi) q3=(rows8-15,kHi)
    uint32_t a_rowbase[4];
    int      a_sw[4];
    const int a_cq = q >> 1;
#pragma unroll
    for (int mi = 0; mi < 4; ++mi) {
        int row = wm * 64 + mi * 16 + (q & 1) * 8 + rr;
        a_rowbase[mi] = as_base + row * DD;
        a_sw[mi] = row & 7;
    }
    // B x4 per n16 pair: q0=(n0-7,kLo) q1=(n0-7,kHi) q2=(n8-15,kLo) q3=(n8-15,kHi)
    uint32_t b_rowbase[2];
    int      b_sw[2];
    const int b_cq = q & 1;
#pragma unroll
    for (int p = 0; p < 2; ++p) {
        int n = wn * 32 + p * 16 + (q >> 1) * 8 + rr;
        b_rowbase[p] = bs_base + n * DD;
        b_sw[p] = n & 7;
    }

    float acc[4][4][4];
#pragma unroll
    for (int mi = 0; mi < 4; ++mi)
#pragma unroll
        for (int ni = 0; ni < 4; ++ni)
#pragma unroll
            for (int e = 0; e < 4; ++e) acc[mi][ni][e] = 0.0f;

#pragma unroll
    for (int kk = 0; kk < DD / 32; ++kk) {     // 4 k32 steps
        const int cb = kk * 2;                 // base 16B chunk index
        uint32_t af[4][4];
#pragma unroll
        for (int mi = 0; mi < 4; ++mi)
            ldsm_x4(af[mi][0], af[mi][1], af[mi][2], af[mi][3],
                    a_rowbase[mi] + (((cb + a_cq) ^ a_sw[mi]) << 4));
        uint32_t bf[2][4];
#pragma unroll
        for (int p = 0; p < 2; ++p)
            ldsm_x4(bf[p][0], bf[p][1], bf[p][2], bf[p][3],
                    b_rowbase[p] + (((cb + b_cq) ^ b_sw[p]) << 4));
#pragma unroll
        for (int mi = 0; mi < 4; ++mi) {
#pragma unroll
            for (int p = 0; p < 2; ++p) {
                mma_fp8(acc[mi][2 * p + 0], af[mi][0], af[mi][1], af[mi][2], af[mi][3],
                        bf[p][0], bf[p][1]);
                mma_fp8(acc[mi][2 * p + 1], af[mi][0], af[mi][1], af[mi][2], af[mi][3],
                        bf[p][2], bf[p][3]);
            }
        }
    }
    __syncthreads();   // sV/sLi/sLj visible; tile reads done

    // ---------------- Epilogue ----------------
#pragma unroll
    for (int mi = 0; mi < 4; ++mi) {
        const int row0 = wm * 64 + mi * 16 + g;
        const int row1 = row0 + 8;
        const int li0 = sLi[row0], li1 = sLi[row1];
        float v0 = 0.0f, v1 = 0.0f;
#pragma unroll
        for (int ni = 0; ni < 4; ++ni) {
            const int colb = wn * 32 + ni * 8 + 2 * l4;
            const int ljA = sLj[colb], ljB = sLj[colb + 1];
#pragma unroll
            for (int e = 0; e < 4; ++e) {
                const float s = acc[mi][ni][e];
                const int li  = (e & 2) ? li1 : li0;
                const int lj  = (e & 1) ? ljB : ljA;
                if (li != lj) {
                    float ev = __expf(MARGIN + s);
                    if (e & 2) v1 += ev; else v0 += ev;
                } else {
                    int gi = bi + ((e & 2) ? row1 : row0);
                    int gj = bj + colb + (e & 1);
                    if (gi != gj) {
                        int idx = atomicAdd(&g_pair_cnt, 1);
                        if (idx < MAXP) { g_pi[idx] = gi; g_pj[idx] = gj; }
                    }
                }
            }
        }
        v0 += __shfl_xor_sync(0xffffffffu, v0, 1);
        v0 += __shfl_xor_sync(0xffffffffu, v0, 2);
        v1 += __shfl_xor_sync(0xffffffffu, v1, 1);
        v1 += __shfl_xor_sync(0xffffffffu, v1, 2);
        if (l4 == 0) {
            atomicAdd(&sV[row0], v0);
            atomicAdd(&sV[row1], v1);
        }
    }
    __syncthreads();
    if (tid < BM) atomicAdd(&g_V[bi + tid], sV[tid]);
}

// ---------------------------------------------------------------------------
// Kernel 2: hinge over positive pairs. One warp per pair; S_ij recomputed
// EXACTLY in f32 from the original inputs (fp8 GEMM error never touches S_ij).
// ---------------------------------------------------------------------------
__global__ void k_pairs(const float* __restrict__ A, const float* __restrict__ B) {
    int n = g_pair_cnt;
    if (n > MAXP) n = MAXP;
    const int lane   = threadIdx.x & 31;
    const int warp   = (blockIdx.x * blockDim.x + threadIdx.x) >> 5;
    const int nwarps = (gridDim.x * blockDim.x) >> 5;

    float local = 0.0f;
    for (int p = warp; p < n; p += nwarps) {
        int i = g_pi[p], j = g_pj[p];
        float4 va = ((const float4*)A)[i * (DD / 4) + lane];
        float4 vb = ((const float4*)B)[j * (DD / 4) + lane];
        float s = va.x * vb.x + va.y * vb.y + va.z * vb.z + va.w * vb.w;
        s += __shfl_xor_sync(0xffffffffu, s, 16);
        s += __shfl_xor_sync(0xffffffffu, s, 8);
        s += __shfl_xor_sync(0xffffffffu, s, 4);
        s += __shfl_xor_sync(0xffffffffu, s, 2);
        s += __shfl_xor_sync(0xffffffffu, s, 1);
        if (lane == 0) {
            float v = g_V[i] + g_V[j];
            float h = fmaxf(logf(v) - s, 0.0f);
            local += h * h;
        }
    }
    // block reduce (lane-0 values only are nonzero)
    local += __shfl_xor_sync(0xffffffffu, local, 16);
    local += __shfl_xor_sync(0xffffffffu, local, 8);
    local += __shfl_xor_sync(0xffffffffu, local, 4);
    local += __shfl_xor_sync(0xffffffffu, local, 2);
    local += __shfl_xor_sync(0xffffffffu, local, 1);

    __shared__ float wsum[8];
    int w = threadIdx.x >> 5;
    if (lane == 0) wsum[w] = local;
    __syncthreads();
    if (threadIdx.x == 0) {
        float s = 0.0f;
        int nw = (blockDim.x + 31) >> 5;
        for (int i = 0; i < nw; ++i) s += wsum[i];
        atomicAdd(&g_loss_sum, s);
    }
}

// ---------------------------------------------------------------------------
// Kernel 3: final scalar
// ---------------------------------------------------------------------------
__global__ void k_final(float* out) {
    out[0] = g_loss_sum / (2.0f * (float)g_pair_cnt);
}

// ---------------------------------------------------------------------------
extern "C" void kernel_launch(void* const* d_in, const int* in_sizes, int n_in,
                              void* d_out, int out_size) {
    const float* a      = (const float*)d_in[0];
    const float* b      = (const float*)d_in[1];
    const int*   labels = (const int*)d_in[2];
    float*       out    = (float*)d_out;

    k_convert<<<(NN * DD / 4) / 256, 256>>>(a, b);

    dim3 grid(NN / BN, NN / BM);   // 64 x 64
    k_gemm<<<grid, THREADS>>>(labels);

    k_pairs<<<512, 256>>>(a, b);
    k_final<<<1, 1>>>(out);
}

// round 6
// speedup vs baseline: 1.0167x; 1.0167x over previous
#include <cuda_runtime.h>
#include <cuda_fp16.h>
#include <cstdint>

// Problem constants
#define NN 8192
#define DD 128
static constexpr float MARGIN = 1.0f;

// Tiling: one CTA tile = 128x128, full K=128 resident in smem (f16 = 32KB/tile)
static constexpr int BM = 128, BN = 128;
static constexpr int THREADS = 256;           // 8 warps: 2 (m) x 4 (n)
static constexpr int MAXP = 1 << 20;
static constexpr int PAIR_BLOCKS = 512;

// ---------------------------------------------------------------------------
// Device globals
// ---------------------------------------------------------------------------
__device__ float g_V[NN];
__device__ float g_loss_sum;
__device__ int   g_pair_cnt;
__device__ int   g_done_blocks;
__device__ int   g_pi[MAXP];
__device__ int   g_pj[MAXP];
__device__ __align__(16) __half g_Ah[NN * DD];
__device__ __align__(16) __half g_Bh[NN * DD];

// ---------------------------------------------------------------------------
// PTX helpers
// ---------------------------------------------------------------------------
__device__ __forceinline__ void ldsm_x4(uint32_t& r0, uint32_t& r1, uint32_t& r2, uint32_t& r3,
                                        uint32_t saddr) {
    asm volatile("ldmatrix.sync.aligned.m8n8.x4.shared.b16 {%0,%1,%2,%3}, [%4];"
                 : "=r"(r0), "=r"(r1), "=r"(r2), "=r"(r3) : "r"(saddr));
}
// fp16 MMA with fp16 accumulate: D(2 regs) = A(4) * B(2) + D
__device__ __forceinline__ void mma_f16acc(uint32_t* d,
                                           uint32_t a0, uint32_t a1, uint32_t a2, uint32_t a3,
                                           uint32_t b0, uint32_t b1) {
    asm volatile(
        "mma.sync.aligned.m16n8k16.row.col.f16.f16.f16.f16 "
        "{%0,%1}, {%2,%3,%4,%5}, {%6,%7}, {%0,%1};"
        : "+r"(d[0]), "+r"(d[1])
        : "r"(a0), "r"(a1), "r"(a2), "r"(a3), "r"(b0), "r"(b1));
}
__device__ __forceinline__ uint32_t h2u(__half2 h) {
    return *reinterpret_cast<uint32_t*>(&h);
}

// ---------------------------------------------------------------------------
// Kernel 0: f32 -> f16 conversion + accumulator zeroing (every replay)
// ---------------------------------------------------------------------------
__global__ void k_convert(const float* __restrict__ A, const float* __restrict__ B) {
    int t = blockIdx.x * blockDim.x + threadIdx.x;     // 0 .. NN*DD/4-1
    float4 va = ((const float4*)A)[t];
    float4 vb = ((const float4*)B)[t];
    uint2 ua = make_uint2(h2u(__floats2half2_rn(va.x, va.y)),
                          h2u(__floats2half2_rn(va.z, va.w)));
    uint2 ub = make_uint2(h2u(__floats2half2_rn(vb.x, vb.y)),
                          h2u(__floats2half2_rn(vb.z, vb.w)));
    ((uint2*)g_Ah)[t] = ua;
    ((uint2*)g_Bh)[t] = ub;
    if (t < NN) g_V[t] = 0.0f;
    if (t == 0) { g_loss_sum = 0.0f; g_pair_cnt = 0; g_done_blocks = 0; }
}

// ---------------------------------------------------------------------------
// Kernel 1: fp16 mma.sync (f16 accum) GEMM S = A * B^T, fused epilogue:
//   V[i] += sum_{labels differ} exp(MARGIN + S_ij); capture positive (i,j).
// ---------------------------------------------------------------------------
__global__ __launch_bounds__(THREADS, 2)
void k_gemm(const int* __restrict__ labels) {
    __shared__ __align__(16) __half As[BM * DD];   // 32 KB
    __shared__ __align__(16) __half Bs[BN * DD];   // 32 KB
    __shared__ float sV[BM];
    __shared__ int   sLi[BM];
    __shared__ int   sLj[BN];

    const int tid  = threadIdx.x;
    const int wid  = tid >> 5;
    const int lane = tid & 31;
    const int g    = lane >> 2;       // 0..7
    const int l4   = lane & 3;        // 0..3
    const int wm   = wid >> 2;        // 0..1 -> m offset 64*wm
    const int wn   = wid & 3;         // 0..3 -> n offset 32*wn
    const int bi   = blockIdx.y * BM;
    const int bj   = blockIdx.x * BN;

    if (tid < BM) { sV[tid] = 0.0f; sLi[tid] = labels[bi + tid]; }
    else if (tid < BM + BN) { sLj[tid - BM] = labels[bj + (tid - BM)]; }

    // Load full K=128 tiles: rows of 256 B = 16 chunks of 16 B, swizzle ^ (row&7)
    // (swizzle on chunk bits 0..2 only keeps ldmatrix-row conflicts away; the
    //  16-chunk row uses (cc & 8) untouched so layout stays addressable)
#pragma unroll
    for (int t = 0; t < 8; ++t) {
        int idx = tid + t * THREADS;           // 0..2047
        int row = idx >> 4;                    // 0..127
        int cc  = idx & 15;                    // 16B chunk 0..15
        int sw  = (cc & 8) | ((cc & 7) ^ (row & 7));
        *(uint4*)&As[row * DD + sw * 8] =
            *(const uint4*)&g_Ah[(size_t)(bi + row) * DD + cc * 8];
        *(uint4*)&Bs[row * DD + sw * 8] =
            *(const uint4*)&g_Bh[(size_t)(bj + row) * DD + cc * 8];
    }
    __syncthreads();

    const uint32_t as_base = (uint32_t)__cvta_generic_to_shared(As);
    const uint32_t bs_base = (uint32_t)__cvta_generic_to_shared(Bs);

    // ldmatrix lane->address precompute
    const int q  = lane >> 3;     // matrix index 0..3
    const int rr = lane & 7;      // row within matrix
    uint32_t a_rowbase[4];
    int      a_sw[4];
    const int a_cq = q >> 1;      // A: q2,q3 are the +16B k-half
#pragma unroll
    for (int mi = 0; mi < 4; ++mi) {
        int row = wm * 64 + mi * 16 + (q & 1) * 8 + rr;
        a_rowbase[mi] = as_base + row * (DD * 2);
        a_sw[mi] = row & 7;
    }
    uint32_t b_rowbase[2];
    int      b_sw[2];
    const int b_cq = q & 1;       // B: q1,q3 are the +16B k-half
#pragma unroll
    for (int p = 0; p < 2; ++p) {
        int n = wn * 32 + p * 16 + (q >> 1) * 8 + rr;
        b_rowbase[p] = bs_base + n * (DD * 2);
        b_sw[p] = n & 7;
    }

    uint32_t acc[4][4][2];
#pragma unroll
    for (int mi = 0; mi < 4; ++mi)
#pragma unroll
        for (int ni = 0; ni < 4; ++ni) { acc[mi][ni][0] = 0u; acc[mi][ni][1] = 0u; }

#pragma unroll
    for (int kk = 0; kk < DD / 16; ++kk) {     // 8 k16 steps
        const int cb = kk * 2;                 // base 16B chunk index (0..14)
        uint32_t af[4][4];
#pragma unroll
        for (int mi = 0; mi < 4; ++mi) {
            int c = cb + a_cq;
            int swc = (c & 8) | ((c & 7) ^ a_sw[mi]);
            ldsm_x4(af[mi][0], af[mi][1], af[mi][2], af[mi][3],
                    a_rowbase[mi] + (swc << 4));
        }
        uint32_t bf[2][4];
#pragma unroll
        for (int p = 0; p < 2; ++p) {
            int c = cb + b_cq;
            int swc = (c & 8) | ((c & 7) ^ b_sw[p]);
            ldsm_x4(bf[p][0], bf[p][1], bf[p][2], bf[p][3],
                    b_rowbase[p] + (swc << 4));
        }
#pragma unroll
        for (int mi = 0; mi < 4; ++mi) {
#pragma unroll
            for (int p = 0; p < 2; ++p) {
                mma_f16acc(acc[mi][2 * p + 0], af[mi][0], af[mi][1], af[mi][2], af[mi][3],
                           bf[p][0], bf[p][1]);
                mma_f16acc(acc[mi][2 * p + 1], af[mi][0], af[mi][1], af[mi][2], af[mi][3],
                           bf[p][2], bf[p][3]);
            }
        }
    }
    __syncthreads();

    // ---------------- Epilogue ----------------
#pragma unroll
    for (int mi = 0; mi < 4; ++mi) {
        const int row0 = wm * 64 + mi * 16 + g;
        const int row1 = row0 + 8;
        const int li0 = sLi[row0], li1 = sLi[row1];
        float v0 = 0.0f, v1 = 0.0f;
#pragma unroll
        for (int ni = 0; ni < 4; ++ni) {
            const int colb = wn * 32 + ni * 8 + 2 * l4;
            const int ljA = sLj[colb], ljB = sLj[colb + 1];
            float2 f0 = __half22float2(*reinterpret_cast<__half2*>(&acc[mi][ni][0])); // row0: colb, colb+1
            float2 f1 = __half22float2(*reinterpret_cast<__half2*>(&acc[mi][ni][1])); // row1: colb, colb+1
            // row0 / colA
            if (li0 != ljA) v0 += __expf(MARGIN + f0.x);
            else { int gi = bi + row0, gj = bj + colb;
                   if (gi != gj) { int x = atomicAdd(&g_pair_cnt, 1); if (x < MAXP) { g_pi[x] = gi; g_pj[x] = gj; } } }
            // row0 / colB
            if (li0 != ljB) v0 += __expf(MARGIN + f0.y);
            else { int gi = bi + row0, gj = bj + colb + 1;
                   if (gi != gj) { int x = atomicAdd(&g_pair_cnt, 1); if (x < MAXP) { g_pi[x] = gi; g_pj[x] = gj; } } }
            // row1 / colA
            if (li1 != ljA) v1 += __expf(MARGIN + f1.x);
            else { int gi = bi + row1, gj = bj + colb;
                   if (gi != gj) { int x = atomicAdd(&g_pair_cnt, 1); if (x < MAXP) { g_pi[x] = gi; g_pj[x] = gj; } } }
            // row1 / colB
            if (li1 != ljB) v1 += __expf(MARGIN + f1.y);
            else { int gi = bi + row1, gj = bj + colb + 1;
                   if (gi != gj) { int x = atomicAdd(&g_pair_cnt, 1); if (x < MAXP) { g_pi[x] = gi; g_pj[x] = gj; } } }
        }
        v0 += __shfl_xor_sync(0xffffffffu, v0, 1);
        v0 += __shfl_xor_sync(0xffffffffu, v0, 2);
        v1 += __shfl_xor_sync(0xffffffffu, v1, 1);
        v1 += __shfl_xor_sync(0xffffffffu, v1, 2);
        if (l4 == 0) {
            atomicAdd(&sV[row0], v0);
            atomicAdd(&sV[row1], v1);
        }
    }
    __syncthreads();
    if (tid < BM) atomicAdd(&g_V[bi + tid], sV[tid]);
}

// ---------------------------------------------------------------------------
// Kernel 2: hinge over positive pairs (exact f32 S_ij recompute) + final scalar
// ---------------------------------------------------------------------------
__global__ void k_pairs(const float* __restrict__ A, const float* __restrict__ B,
                        float* __restrict__ out) {
    int n = g_pair_cnt;
    if (n > MAXP) n = MAXP;
    const int lane   = threadIdx.x & 31;
    const int warp   = (blockIdx.x * blockDim.x + threadIdx.x) >> 5;
    const int nwarps = (gridDim.x * blockDim.x) >> 5;

    float local = 0.0f;
    for (int p = warp; p < n; p += nwarps) {
        int i = g_pi[p], j = g_pj[p];
        float4 va = ((const float4*)A)[i * (DD / 4) + lane];
        float4 vb = ((const float4*)B)[j * (DD / 4) + lane];
        float s = va.x * vb.x + va.y * vb.y + va.z * vb.z + va.w * vb.w;
        s += __shfl_xor_sync(0xffffffffu, s, 16);
        s += __shfl_xor_sync(0xffffffffu, s, 8);
        s += __shfl_xor_sync(0xffffffffu, s, 4);
        s += __shfl_xor_sync(0xffffffffu, s, 2);
        s += __shfl_xor_sync(0xffffffffu, s, 1);
        if (lane == 0) {
            float v = g_V[i] + g_V[j];
            float h = fmaxf(logf(v) - s, 0.0f);
            local += h * h;
        }
    }
    local += __shfl_xor_sync(0xffffffffu, local, 16);
    local += __shfl_xor_sync(0xffffffffu, local, 8);
    local += __shfl_xor_sync(0xffffffffu, local, 4);
    local += __shfl_xor_sync(0xffffffffu, local, 2);
    local += __shfl_xor_sync(0xffffffffu, local, 1);

    __shared__ float wsum[8];
    int w = threadIdx.x >> 5;
    if (lane == 0) wsum[w] = local;
    __syncthreads();
    if (threadIdx.x == 0) {
        float s = 0.0f;
        int nw = (blockDim.x + 31) >> 5;
        for (int i = 0; i < nw; ++i) s += wsum[i];
        atomicAdd(&g_loss_sum, s);
        __threadfence();
        int done = atomicAdd(&g_done_blocks, 1);
        if (done == gridDim.x - 1) {
            // all blocks' g_loss_sum contributions are visible
            out[0] = g_loss_sum / (2.0f * (float)g_pair_cnt);
        }
    }
}

// ---------------------------------------------------------------------------
extern "C" void kernel_launch(void* const* d_in, const int* in_sizes, int n_in,
                              void* d_out, int out_size) {
    const float* a      = (const float*)d_in[0];
    const float* b      = (const float*)d_in[1];
    const int*   labels = (const int*)d_in[2];
    float*       out    = (float*)d_out;

    k_convert<<<(NN * DD / 4) / 256, 256>>>(a, b);

    dim3 grid(NN / BN, NN / BM);   // 64 x 64
    k_gemm<<<grid, THREADS>>>(labels);

    k_pairs<<<PAIR_BLOCKS, 256>>>(a, b, out);
}